// round 1
// baseline (speedup 1.0000x reference)
#include <cuda_runtime.h>
#include <math.h>

// Problem constants (fixed shapes from reference setup_inputs)
#define BATCH 8
#define LEN   4096
#define INP   1024
#define STATE 512
#define KHALF 256          // STATE/2 complex channels
#define OUTD  1024
#define ROWS  (BATCH*LEN)  // 32768
#define CHUNK 64
#define NCHUNK (LEN/CHUNK) // 64
#define EPSV 1e-6f

// -------- scratch (static device globals; no allocation in kernel_launch) ----
__device__ float  g_uB[(size_t)ROWS * STATE];   // (rows, 512) = un @ B
__device__ float  g_x [(size_t)ROWS * STATE];   // (rows, 512) scan output
__device__ float  g_rowscale[ROWS];
__device__ float2 g_localF[BATCH * NCHUNK * KHALF];
__device__ float2 g_carry [BATCH * NCHUNK * KHALF];

// ---------------------------------------------------------------- rmsnorm row scale
__global__ void rowscale_kernel(const float* __restrict__ u) {
    int row = blockIdx.x;
    const float4* up = reinterpret_cast<const float4*>(u + (size_t)row * INP);
    float s = 0.f;
    // 256 threads, 256 float4 per row -> 1 each
    float4 v = up[threadIdx.x];
    s = v.x*v.x + v.y*v.y + v.z*v.z + v.w*v.w;
    #pragma unroll
    for (int o = 16; o; o >>= 1) s += __shfl_xor_sync(0xffffffffu, s, o);
    __shared__ float red[8];
    if ((threadIdx.x & 31) == 0) red[threadIdx.x >> 5] = s;
    __syncthreads();
    if (threadIdx.x < 32) {
        s = (threadIdx.x < 8) ? red[threadIdx.x] : 0.f;
        #pragma unroll
        for (int o = 4; o; o >>= 1) s += __shfl_xor_sync(0xffffffffu, s, o);
        if (threadIdx.x == 0) g_rowscale[row] = rsqrtf(s * (1.0f / INP) + EPSV);
    }
}

// ---------------------------------------------------------------- SGEMM 128x128x8
// C[M,N] = Aop[M,K] * B[K,N], all row-major.
// If SCALE_A: Aop[m,k] = A[m,k] * g_rowscale[m] * colscale[k]  (fused rmsnorm)
template<bool SCALE_A>
__global__ void __launch_bounds__(256) sgemm_kernel(
    const float* __restrict__ A, const float* __restrict__ B,
    float* __restrict__ Cout, int M, int N, int Kd,
    const float* __restrict__ colscale)
{
    __shared__ float As[8][128];
    __shared__ float Bs[8][128];

    const int tid  = threadIdx.x;
    const int bm   = blockIdx.y * 128;
    const int bn   = blockIdx.x * 128;
    const int trow = tid >> 4;        // 0..15
    const int tcol = tid & 15;        // 0..15

    // A tile load mapping: 128 rows x 8 k, one float4 per thread
    const int arow  = tid >> 1;       // 0..127
    const int akcol = (tid & 1) * 4;  // 0 or 4
    // B tile load mapping: 8 k rows x 128 cols, one float4 per thread
    const int brow = tid >> 5;        // 0..7
    const int bcol = (tid & 31) * 4;  // 0..124

    float rs = 1.f;
    if (SCALE_A) rs = g_rowscale[bm + arow];

    const float* Aptr = A + (size_t)(bm + arow) * Kd + akcol;
    const float* Bptr = B + (size_t)brow * N + bn + bcol;

    float acc[8][8];
    #pragma unroll
    for (int i = 0; i < 8; i++)
        #pragma unroll
        for (int j = 0; j < 8; j++) acc[i][j] = 0.f;

    for (int k0 = 0; k0 < Kd; k0 += 8) {
        float4 av = *reinterpret_cast<const float4*>(Aptr);
        if (SCALE_A) {
            float4 cs = *reinterpret_cast<const float4*>(colscale + k0 + akcol);
            av.x *= rs * cs.x; av.y *= rs * cs.y;
            av.z *= rs * cs.z; av.w *= rs * cs.w;
        }
        As[akcol + 0][arow] = av.x;
        As[akcol + 1][arow] = av.y;
        As[akcol + 2][arow] = av.z;
        As[akcol + 3][arow] = av.w;

        float4 bv = *reinterpret_cast<const float4*>(Bptr);
        *reinterpret_cast<float4*>(&Bs[brow][bcol]) = bv;

        __syncthreads();

        #pragma unroll
        for (int kk = 0; kk < 8; kk++) {
            float ar[8], br[8];
            *reinterpret_cast<float4*>(ar)     = *reinterpret_cast<const float4*>(&As[kk][trow * 4]);
            *reinterpret_cast<float4*>(ar + 4) = *reinterpret_cast<const float4*>(&As[kk][64 + trow * 4]);
            *reinterpret_cast<float4*>(br)     = *reinterpret_cast<const float4*>(&Bs[kk][tcol * 4]);
            *reinterpret_cast<float4*>(br + 4) = *reinterpret_cast<const float4*>(&Bs[kk][64 + tcol * 4]);
            #pragma unroll
            for (int i = 0; i < 8; i++)
                #pragma unroll
                for (int j = 0; j < 8; j++)
                    acc[i][j] = fmaf(ar[i], br[j], acc[i][j]);
        }
        __syncthreads();

        Aptr += 8;
        Bptr += (size_t)8 * N;
    }

    #pragma unroll
    for (int i = 0; i < 8; i++) {
        int r = bm + ((i < 4) ? (trow * 4 + i) : (64 + trow * 4 + i - 4));
        float* cp = Cout + (size_t)r * N + bn;
        *reinterpret_cast<float4*>(cp + tcol * 4)      = make_float4(acc[i][0], acc[i][1], acc[i][2], acc[i][3]);
        *reinterpret_cast<float4*>(cp + 64 + tcol * 4) = make_float4(acc[i][4], acc[i][5], acc[i][6], acc[i][7]);
    }
}

// ---------------------------------------------------------------- complex helpers
__device__ __forceinline__ float2 cmul(float2 a, float2 b) {
    return make_float2(a.x * b.x - a.y * b.y, a.x * b.y + a.y * b.x);
}
// a*z + w
__device__ __forceinline__ float2 cmad(float2 a, float2 z, float2 w) {
    return make_float2(fmaf(a.x, z.x, fmaf(-a.y, z.y, w.x)),
                       fmaf(a.x, z.y, fmaf( a.y, z.x, w.y)));
}

// Phase A: chunk-local scans from zero state -> local finals
__global__ void scan_local_kernel(const float* __restrict__ Amat) {
    const int k     = threadIdx.x;       // 0..255 complex channel
    const int b     = blockIdx.x >> 6;   // / NCHUNK
    const int chunk = blockIdx.x & (NCHUNK - 1);
    const float2 a = make_float2(Amat[k * 4 + 0], Amat[k * 4 + 1]);
    const float2* w = reinterpret_cast<const float2*>(g_uB)
                    + ((size_t)(b * LEN + chunk * CHUNK)) * KHALF + k;
    float2 z = make_float2(0.f, 0.f);
    #pragma unroll 8
    for (int j = 0; j < CHUNK; j++) {
        float2 wv = *w; w += KHALF;
        z = cmad(a, z, wv);
    }
    g_localF[(b * NCHUNK + chunk) * KHALF + k] = z;
}

// Phase B: cross-chunk carry scan (2048 threads)
__global__ void scan_carry_kernel(const float* __restrict__ Amat,
                                  const float* __restrict__ x0) {
    int idx = blockIdx.x * blockDim.x + threadIdx.x;
    if (idx >= BATCH * KHALF) return;
    const int b = idx / KHALF, k = idx % KHALF;
    float2 a = make_float2(Amat[k * 4 + 0], Amat[k * 4 + 1]);
    float2 a64 = a;
    #pragma unroll
    for (int i = 0; i < 6; i++) a64 = cmul(a64, a64);  // a^64
    float2 z = make_float2(x0[(b * KHALF + k) * 2], x0[(b * KHALF + k) * 2 + 1]);
    g_carry[(b * NCHUNK + 0) * KHALF + k] = z;
    for (int c = 1; c < NCHUNK; c++) {
        float2 F = g_localF[(b * NCHUNK + c - 1) * KHALF + k];
        z = cmad(a64, z, F);
        g_carry[(b * NCHUNK + c) * KHALF + k] = z;
    }
}

// Phase C: final scan with correct init; writes x and new_state
__global__ void scan_final_kernel(const float* __restrict__ Amat,
                                  float2* __restrict__ ns_out) {
    const int k     = threadIdx.x;
    const int b     = blockIdx.x >> 6;
    const int chunk = blockIdx.x & (NCHUNK - 1);
    const float2 a = make_float2(Amat[k * 4 + 0], Amat[k * 4 + 1]);
    float2 z = g_carry[(b * NCHUNK + chunk) * KHALF + k];
    const float2* w = reinterpret_cast<const float2*>(g_uB)
                    + ((size_t)(b * LEN + chunk * CHUNK)) * KHALF + k;
    float2* xp = reinterpret_cast<float2*>(g_x)
               + ((size_t)(b * LEN + chunk * CHUNK)) * KHALF + k;
    #pragma unroll 8
    for (int j = 0; j < CHUNK; j++) {
        float2 wv = *w; w += KHALF;
        z = cmad(a, z, wv);
        *xp = z; xp += KHALF;
    }
    if (chunk == NCHUNK - 1) ns_out[b * KHALF + k] = z;
}

// ---------------------------------------------------------------- launch
extern "C" void kernel_launch(void* const* d_in, const int* in_sizes, int n_in,
                              void* d_out, int out_size) {
    const float* u  = (const float*)d_in[0];   // (8,4096,1024)
    const float* x0 = (const float*)d_in[1];   // (8,256,2)
    const float* A  = (const float*)d_in[2];   // (256,2,2)
    const float* B  = (const float*)d_in[3];   // (1024,512)
    const float* C  = (const float*)d_in[4];   // (512,1024)
    const float* nw = (const float*)d_in[5];   // (1024,)
    float* out = (float*)d_out;                // y (8,4096,1024) then new_state (8,256,2)

    float* d_uB;
    float* d_x;
    cudaGetSymbolAddress((void**)&d_uB, g_uB);
    cudaGetSymbolAddress((void**)&d_x,  g_x);

    // 1) rmsnorm row scales
    rowscale_kernel<<<ROWS, 256>>>(u);

    // 2) uB = (u * rowscale * nw) @ B   -> g_uB (32768 x 512)
    {
        dim3 grid(STATE / 128, ROWS / 128);   // (4, 256)
        sgemm_kernel<true><<<grid, 256>>>(u, B, d_uB, ROWS, STATE, INP, nw);
    }

    // 3) chunked complex scan
    scan_local_kernel<<<BATCH * NCHUNK, KHALF>>>(A);
    scan_carry_kernel<<<(BATCH * KHALF + 255) / 256, 256>>>(A, x0);
    {
        float2* ns_out = reinterpret_cast<float2*>(out + (size_t)ROWS * OUTD);
        scan_final_kernel<<<BATCH * NCHUNK, KHALF>>>(A, ns_out);
    }

    // 4) y = x @ C   -> d_out (32768 x 1024)
    {
        dim3 grid(OUTD / 128, ROWS / 128);    // (8, 256)
        sgemm_kernel<false><<<grid, 256>>>(d_x, C, out, ROWS, OUTD, STATE, nullptr);
    }
}

// round 4
// speedup vs baseline: 4.6887x; 4.6887x over previous
#include <cuda_runtime.h>
#include <cuda_fp16.h>
#include <cstdint>
#include <math.h>

// ---------------- problem constants ----------------
#define BATCH 8
#define LEN   4096
#define INP   1024
#define STATE 512
#define KHALF 256
#define OUTD  1024
#define ROWS  (BATCH*LEN)      // 32768
#define CHUNK 64
#define NCHUNK (LEN/CHUNK)     // 64
#define EPSV 1e-6f

// ---------------- scratch (device globals; no runtime allocation) ----------------
__device__ __half g_uh[(size_t)ROWS * INP];      // rmsnormed u, fp16
__device__ float  g_uB[(size_t)ROWS * STATE];    // un @ B, fp32
__device__ __half g_xh[(size_t)ROWS * STATE];    // scan output, fp16
__device__ __half g_Bt[(size_t)STATE * INP];     // B^T  (512 x 1024)
__device__ __half g_Ct[(size_t)OUTD  * STATE];   // C^T  (1024 x 512)
__device__ float2 g_localF[BATCH * NCHUNK * KHALF];
__device__ float2 g_carry [BATCH * NCHUNK * KHALF];

// ---------------- helpers ----------------
__device__ __forceinline__ uint32_t smem_u32(const void* p) {
    uint32_t a;
    asm("{ .reg .u64 t; cvta.to.shared.u64 t, %1; cvt.u32.u64 %0, t; }" : "=r"(a) : "l"(p));
    return a;
}
__device__ __forceinline__ void cp16(uint32_t dst, const void* src) {
    asm volatile("cp.async.cg.shared.global [%0], [%1], 16;" :: "r"(dst), "l"(src));
}
__device__ __forceinline__ void cp_commit() { asm volatile("cp.async.commit_group;"); }
template <int N> __device__ __forceinline__ void cp_wait() {
    asm volatile("cp.async.wait_group %0;" :: "n"(N));
}
__device__ __forceinline__ void ldsm_x4(uint32_t* r, uint32_t addr) {
    asm volatile("ldmatrix.sync.aligned.m8n8.x4.shared.b16 {%0,%1,%2,%3}, [%4];"
                 : "=r"(r[0]), "=r"(r[1]), "=r"(r[2]), "=r"(r[3]) : "r"(addr));
}
// NOTE: non-trans — B tile is stored N x K row-major (k contiguous), which is
// exactly the col-major B operand layout; fragments need k-consecutive pairs.
__device__ __forceinline__ void ldsm_x2(uint32_t* r, uint32_t addr) {
    asm volatile("ldmatrix.sync.aligned.m8n8.x2.shared.b16 {%0,%1}, [%2];"
                 : "=r"(r[0]), "=r"(r[1]) : "r"(addr));
}
__device__ __forceinline__ void mma16816(float* c, const uint32_t* a, const uint32_t* b) {
    asm volatile("mma.sync.aligned.m16n8k16.row.col.f32.f16.f16.f32 "
                 "{%0,%1,%2,%3}, {%4,%5,%6,%7}, {%8,%9}, {%0,%1,%2,%3};"
                 : "+f"(c[0]), "+f"(c[1]), "+f"(c[2]), "+f"(c[3])
                 : "r"(a[0]), "r"(a[1]), "r"(a[2]), "r"(a[3]), "r"(b[0]), "r"(b[1]));
}

// ---------------- prep: fused rmsnorm -> fp16 u ----------------
__global__ void convert_u_kernel(const float* __restrict__ u, const float* __restrict__ nw) {
    const int row = blockIdx.x;
    const int tid = threadIdx.x;
    float4 v = reinterpret_cast<const float4*>(u)[(size_t)row * 256 + tid];
    float s = v.x*v.x + v.y*v.y + v.z*v.z + v.w*v.w;
    #pragma unroll
    for (int o = 16; o; o >>= 1) s += __shfl_xor_sync(0xffffffffu, s, o);
    __shared__ float red[8];
    __shared__ float rs_sh;
    if ((tid & 31) == 0) red[tid >> 5] = s;
    __syncthreads();
    if (tid < 32) {
        s = (tid < 8) ? red[tid] : 0.f;
        #pragma unroll
        for (int o = 4; o; o >>= 1) s += __shfl_xor_sync(0xffffffffu, s, o);
        if (tid == 0) rs_sh = rsqrtf(s * (1.0f / INP) + EPSV);
    }
    __syncthreads();
    const float rs = rs_sh;
    float4 w = reinterpret_cast<const float4*>(nw)[tid];
    __half2* uh2 = reinterpret_cast<__half2*>(g_uh) + (size_t)row * 512 + tid * 2;
    uh2[0] = __floats2half2_rn(v.x * rs * w.x, v.y * rs * w.y);
    uh2[1] = __floats2half2_rn(v.z * rs * w.z, v.w * rs * w.w);
}

// ---------------- prep: transpose weights to fp16 ----------------
__global__ void pack_b_kernel(const float* __restrict__ B) {
    int idx = blockIdx.x * blockDim.x + threadIdx.x;   // over 1024*512
    if (idx >= INP * STATE) return;
    int k = idx / STATE, n = idx % STATE;
    g_Bt[(size_t)n * INP + k] = __float2half_rn(B[idx]);
}
__global__ void pack_c_kernel(const float* __restrict__ C) {
    int idx = blockIdx.x * blockDim.x + threadIdx.x;   // over 512*1024
    if (idx >= STATE * OUTD) return;
    int k = idx / OUTD, n = idx % OUTD;
    g_Ct[(size_t)n * STATE + k] = __float2half_rn(C[idx]);
}

// ---------------- HGEMM: C[M,N](f32) = A[M,K](f16) x Bt[N,K](f16)^T ----------------
#define PITCH   80                 // bytes per smem row (32 halves + pad)
#define STG_A   (128 * PITCH)     // 10240 B
#define STG_SZ  (2 * STG_A)       // A + B per stage
#define NSTAGE  3
#define SM_TOT  (NSTAGE * STG_SZ) // 61440 B

__device__ __forceinline__ void load_stage(uint32_t sbase, int s, int c, int tid,
                                           const __half* __restrict__ Ag,
                                           const __half* __restrict__ Bg,
                                           int m0, int n0, int K) {
    const uint32_t sa = sbase + s * STG_SZ;
    const uint32_t sb = sa + STG_A;
    #pragma unroll
    for (int i = 0; i < 2; i++) {
        int lin = tid + i * 256;
        int row = lin >> 2, ch = lin & 3;
        cp16(sa + row * PITCH + ch * 16,
             Ag + (size_t)(m0 + row) * K + c * 32 + ch * 8);
        cp16(sb + row * PITCH + ch * 16,
             Bg + (size_t)(n0 + row) * K + c * 32 + ch * 8);
    }
}

__global__ void __launch_bounds__(256, 2)
hgemm_kernel(const __half* __restrict__ Ag, const __half* __restrict__ Bg,
             float* __restrict__ Cout, int K, int N) {
    extern __shared__ char smem[];
    const uint32_t sbase = smem_u32(smem);
    const int tid  = threadIdx.x;
    const int lane = tid & 31;
    const int wid  = tid >> 5;
    const int wm   = (wid & 1) * 64;   // warp m offset
    const int wn   = (wid >> 1) * 32;  // warp n offset
    const int m0   = blockIdx.y * 128;
    const int n0   = blockIdx.x * 128;
    const int NC   = K / 32;

    float acc[4][4][4];
    #pragma unroll
    for (int i = 0; i < 4; i++)
        #pragma unroll
        for (int j = 0; j < 4; j++)
            #pragma unroll
            for (int q = 0; q < 4; q++) acc[i][j][q] = 0.f;

    load_stage(sbase, 0, 0, tid, Ag, Bg, m0, n0, K); cp_commit();
    load_stage(sbase, 1, 1, tid, Ag, Bg, m0, n0, K); cp_commit();

    for (int c = 0; c < NC; c++) {
        const int s = c % NSTAGE;
        if (c + 2 < NC) { load_stage(sbase, (c + 2) % NSTAGE, c + 2, tid, Ag, Bg, m0, n0, K); cp_commit(); }
        if (c + 2 < NC)      cp_wait<2>();
        else if (c + 1 < NC) cp_wait<1>();
        else                 cp_wait<0>();
        __syncthreads();

        const uint32_t sa = sbase + s * STG_SZ;
        const uint32_t sb = sa + STG_A;
        #pragma unroll
        for (int ks = 0; ks < 2; ks++) {
            uint32_t afr[4][4];
            #pragma unroll
            for (int mt = 0; mt < 4; mt++) {
                uint32_t addr = sa + (wm + mt * 16 + (lane & 15)) * PITCH
                              + (ks * 16 + (lane >> 4) * 8) * 2;
                ldsm_x4(afr[mt], addr);
            }
            uint32_t bfr[4][2];
            #pragma unroll
            for (int nt = 0; nt < 4; nt++) {
                uint32_t addr = sb + (wn + nt * 8 + (lane & 7)) * PITCH
                              + (ks * 16 + ((lane >> 3) & 1) * 8) * 2;
                ldsm_x2(bfr[nt], addr);
            }
            #pragma unroll
            for (int mt = 0; mt < 4; mt++)
                #pragma unroll
                for (int nt = 0; nt < 4; nt++)
                    mma16816(acc[mt][nt], afr[mt], bfr[nt]);
        }
        __syncthreads();
    }

    // epilogue
    #pragma unroll
    for (int mt = 0; mt < 4; mt++) {
        int r = m0 + wm + mt * 16 + (lane >> 2);
        #pragma unroll
        for (int nt = 0; nt < 4; nt++) {
            int col = n0 + wn + nt * 8 + (lane & 3) * 2;
            *reinterpret_cast<float2*>(Cout + (size_t)r * N + col) =
                make_float2(acc[mt][nt][0], acc[mt][nt][1]);
            *reinterpret_cast<float2*>(Cout + (size_t)(r + 8) * N + col) =
                make_float2(acc[mt][nt][2], acc[mt][nt][3]);
        }
    }
}

// ---------------- complex scan ----------------
__device__ __forceinline__ float2 cmul(float2 a, float2 b) {
    return make_float2(a.x * b.x - a.y * b.y, a.x * b.y + a.y * b.x);
}
__device__ __forceinline__ float2 cmad(float2 a, float2 z, float2 w) {
    return make_float2(fmaf(a.x, z.x, fmaf(-a.y, z.y, w.x)),
                       fmaf(a.x, z.y, fmaf( a.y, z.x, w.y)));
}

__global__ void scan_local_kernel(const float* __restrict__ Amat) {
    const int k = threadIdx.x;
    const int b = blockIdx.x >> 6;
    const int chunk = blockIdx.x & (NCHUNK - 1);
    const float2 a = make_float2(Amat[k * 4 + 0], Amat[k * 4 + 1]);
    const float2* w = reinterpret_cast<const float2*>(g_uB)
                    + ((size_t)(b * LEN + chunk * CHUNK)) * KHALF + k;
    float2 z = make_float2(0.f, 0.f);
    #pragma unroll 8
    for (int j = 0; j < CHUNK; j++) { float2 wv = *w; w += KHALF; z = cmad(a, z, wv); }
    g_localF[(b * NCHUNK + chunk) * KHALF + k] = z;
}

__global__ void scan_carry_kernel(const float* __restrict__ Amat,
                                  const float* __restrict__ x0) {
    int idx = blockIdx.x * blockDim.x + threadIdx.x;
    if (idx >= BATCH * KHALF) return;
    const int b = idx / KHALF, k = idx % KHALF;
    float2 a = make_float2(Amat[k * 4 + 0], Amat[k * 4 + 1]);
    float2 a64 = a;
    #pragma unroll
    for (int i = 0; i < 6; i++) a64 = cmul(a64, a64);
    float2 z = make_float2(x0[(b * KHALF + k) * 2], x0[(b * KHALF + k) * 2 + 1]);
    g_carry[(b * NCHUNK + 0) * KHALF + k] = z;
    for (int g = 0; g < 8; g++) {
        float2 F[8];
        #pragma unroll
        for (int j = 0; j < 8; j++) {
            int ix = g * 8 + j;
            F[j] = (ix < NCHUNK - 1) ? g_localF[(b * NCHUNK + ix) * KHALF + k]
                                     : make_float2(0.f, 0.f);
        }
        #pragma unroll
        for (int j = 0; j < 8; j++) {
            int cc = g * 8 + j + 1;
            if (cc < NCHUNK) { z = cmad(a64, z, F[j]); g_carry[(b * NCHUNK + cc) * KHALF + k] = z; }
        }
    }
}

__global__ void scan_final_kernel(const float* __restrict__ Amat,
                                  float2* __restrict__ ns_out) {
    const int k = threadIdx.x;
    const int b = blockIdx.x >> 6;
    const int chunk = blockIdx.x & (NCHUNK - 1);
    const float2 a = make_float2(Amat[k * 4 + 0], Amat[k * 4 + 1]);
    float2 z = g_carry[(b * NCHUNK + chunk) * KHALF + k];
    const float2* w = reinterpret_cast<const float2*>(g_uB)
                    + ((size_t)(b * LEN + chunk * CHUNK)) * KHALF + k;
    __half2* xh = reinterpret_cast<__half2*>(g_xh)
                + ((size_t)(b * LEN + chunk * CHUNK)) * KHALF + k;
    #pragma unroll 8
    for (int j = 0; j < CHUNK; j++) {
        float2 wv = *w; w += KHALF;
        z = cmad(a, z, wv);
        *xh = __floats2half2_rn(z.x, z.y); xh += KHALF;
    }
    if (chunk == NCHUNK - 1) ns_out[b * KHALF + k] = z;
}

// ---------------- launch ----------------
extern "C" void kernel_launch(void* const* d_in, const int* in_sizes, int n_in,
                              void* d_out, int out_size) {
    const float* u  = (const float*)d_in[0];
    const float* x0 = (const float*)d_in[1];
    const float* A  = (const float*)d_in[2];
    const float* B  = (const float*)d_in[3];
    const float* C  = (const float*)d_in[4];
    const float* nw = (const float*)d_in[5];
    float* out = (float*)d_out;

    __half *d_uh, *d_xh, *d_Bt, *d_Ct;
    float *d_uB;
    cudaGetSymbolAddress((void**)&d_uh, g_uh);
    cudaGetSymbolAddress((void**)&d_xh, g_xh);
    cudaGetSymbolAddress((void**)&d_Bt, g_Bt);
    cudaGetSymbolAddress((void**)&d_Ct, g_Ct);
    cudaGetSymbolAddress((void**)&d_uB, g_uB);

    cudaFuncSetAttribute(hgemm_kernel, cudaFuncAttributeMaxDynamicSharedMemorySize, SM_TOT);

    // 1) fused rmsnorm -> fp16; transpose weights
    convert_u_kernel<<<ROWS, 256>>>(u, nw);
    pack_b_kernel<<<(INP * STATE + 255) / 256, 256>>>(B);
    pack_c_kernel<<<(STATE * OUTD + 255) / 256, 256>>>(C);

    // 2) uB = un @ B  -> fp32 g_uB
    {
        dim3 grid(STATE / 128, ROWS / 128);   // (4, 256)
        hgemm_kernel<<<grid, 256, SM_TOT>>>(d_uh, d_Bt, d_uB, INP, STATE);
    }

    // 3) chunked complex scan -> x (fp16) + new_state
    scan_local_kernel<<<BATCH * NCHUNK, KHALF>>>(A);
    scan_carry_kernel<<<(BATCH * KHALF + 255) / 256, 256>>>(A, x0);
    {
        float2* ns_out = reinterpret_cast<float2*>(out + (size_t)ROWS * OUTD);
        scan_final_kernel<<<BATCH * NCHUNK, KHALF>>>(A, x0 ? (float2*)ns_out : (float2*)ns_out);
    }

    // 4) y = x @ C -> d_out
    {
        dim3 grid(OUTD / 128, ROWS / 128);    // (8, 256)
        hgemm_kernel<<<grid, 256, SM_TOT>>>(d_xh, d_Ct, out, STATE, OUTD);
    }
}